// round 8
// baseline (speedup 1.0000x reference)
#include <cuda_runtime.h>
#include <cstdint>

// Problem constants
#define A_CLS 50
#define C_CL  1024
#define F_LIT 1180
#define B_SMP 512
#define AC    (A_CLS * C_CL)     // 51200 clauses
#define NWORD 40                 // 10 float4-iterations x 4 ballot-words

// Scratch (static __device__ globals — no runtime allocation)
// Bit order: iteration i covers literals [i*128, i*128+128); lane l's float4
// holds literals i*128+l*4 .. +3; ballot word (4i+j) packs component j across
// lanes. The SAME permutation is used for x and ta masks -> logic is exact.
__device__ unsigned d_xbits[B_SMP][NWORD]; // full x masks (rare path only)
__device__ unsigned d_x0[B_SMP];           // dense word-0 copy (fast path)
__device__ float    d_votes[B_SMP * A_CLS];
__device__ unsigned d_done;

// ---------------------------------------------------------------------------
// pack_x: one warp per sample row; float4 loads + ballots. Also zeroes the
// vote accumulator and the completion ticket for this launch/replay.
// ---------------------------------------------------------------------------
__global__ void pack_x_kernel(const float* __restrict__ x) {
    int gtid = blockIdx.x * blockDim.x + threadIdx.x;
    int warp = gtid >> 5;
    int lane = threadIdx.x & 31;
    if (warp < B_SMP) {
        const float4* row4 = reinterpret_cast<const float4*>(x + (size_t)warp * F_LIT);
        #pragma unroll
        for (int i = 0; i < 10; i++) {
            float4 v = make_float4(0.f, 0.f, 0.f, 0.f);
            if (i * 128 + lane * 4 < F_LIT) v = __ldg(&row4[i * 32 + lane]);
            unsigned b0 = __ballot_sync(0xFFFFFFFFu, v.x > 0.5f);
            unsigned b1 = __ballot_sync(0xFFFFFFFFu, v.y > 0.5f);
            unsigned b2 = __ballot_sync(0xFFFFFFFFu, v.z > 0.5f);
            unsigned b3 = __ballot_sync(0xFFFFFFFFu, v.w > 0.5f);
            if (lane == 0) {
                reinterpret_cast<uint4*>(d_xbits[warp])[i] = make_uint4(b0, b1, b2, b3);
                if (i == 0) d_x0[warp] = b0;
            }
        }
    }
    for (int i = gtid; i < B_SMP * A_CLS; i += gridDim.x * blockDim.x)
        d_votes[i] = 0.0f;
    if (gtid == 0) d_done = 0u;
}

// ---------------------------------------------------------------------------
// Fused pack(ta) + clause eval + vote + (last block) clip/store.
// One warp per clause (a,c): it reads its two contiguous ta rows (pos, neg),
// ballots them into 80 mask words (lane l keeps words l and l+32; word 0 is
// kept by every lane), then evaluates all 512 samples against word 0 with a
// single LOP3 each. Candidates (P ~ 2^-32/eval) get a convergent full check
// where each lane tests its resident words and __all_sync decides; fires go
// to global votes via atomicAdd. The DRAM-bound ta read (483 MB) hides all
// of the eval ALU. A ticket counter lets the last block clip + write output.
// ---------------------------------------------------------------------------
__global__ __launch_bounds__(256, 6)
void fused_kernel(const float* __restrict__ ta,
                  const float* __restrict__ clause_sign,
                  const int*   __restrict__ tptr,
                  float*       __restrict__ out) {
    __shared__ __align__(16) unsigned sx0[B_SMP];
    __shared__ bool sLast;

    // cooperative load of all 512 word-0 x masks (2 KB, coalesced uint4)
    for (int i = threadIdx.x; i < B_SMP / 4; i += blockDim.x)
        reinterpret_cast<uint4*>(sx0)[i] =
            reinterpret_cast<const uint4*>(d_x0)[i];
    __syncthreads();

    int warp = blockIdx.x * (blockDim.x >> 5) + (threadIdx.x >> 5);
    int lane = threadIdx.x & 31;
    int ac   = warp;                  // grid sized so warp < AC exactly
    int a    = ac >> 10;              // C_CL == 1024

    // ---- pack this clause's masks (streaming reads, evict-first) ----
    const float4* pos4 = reinterpret_cast<const float4*>(ta + (size_t)ac * 2 * F_LIT);
    const float4* neg4 = pos4 + (F_LIT / 4);   // 295 float4 = 1180 floats
    unsigned p_lo = 0, n_lo = 0, p_hi = 0, n_hi = 0, p0 = 0, n0 = 0;
    #pragma unroll
    for (int i = 0; i < 10; i++) {
        float4 vp = make_float4(0.f, 0.f, 0.f, 0.f);
        float4 vn = make_float4(0.f, 0.f, 0.f, 0.f);
        if (i * 128 + lane * 4 < F_LIT) {
            vp = __ldcs(&pos4[i * 32 + lane]);
            vn = __ldcs(&neg4[i * 32 + lane]);
        }
        #pragma unroll
        for (int j = 0; j < 4; j++) {
            float fp = (j == 0) ? vp.x : (j == 1) ? vp.y : (j == 2) ? vp.z : vp.w;
            float fn = (j == 0) ? vn.x : (j == 1) ? vn.y : (j == 2) ? vn.z : vn.w;
            unsigned bp = __ballot_sync(0xFFFFFFFFu, fp > 16.0f);
            unsigned bn = __ballot_sync(0xFFFFFFFFu, fn > 16.0f);
            int w = 4 * i + j;
            if (w == 0)         { p0 = bp;   n0 = bn;   }
            if (w == lane)      { p_lo = bp; n_lo = bn; }
            if (w == lane + 32) { p_hi = bp; n_hi = bn; }
        }
    }

    // ---- fast-path eval: 512 samples, 1 LOP3 each, word-0 screen ----
    float sg = __ldg(&clause_sign[ac]);
    unsigned cand = 0;
    #pragma unroll
    for (int g = 0; g < 4; g++) {
        // lane l handles samples g*128 + 4l .. +3 (conflict-free LDS.128)
        uint4 x = *reinterpret_cast<const uint4*>(&sx0[g * 128 + lane * 4]);
        unsigned v0 = (p0 & ~x.x) | (n0 & x.x);
        unsigned v1 = (p0 & ~x.y) | (n0 & x.y);
        unsigned v2 = (p0 & ~x.z) | (n0 & x.z);
        unsigned v3 = (p0 & ~x.w) | (n0 & x.w);
        if (min(min(v0, v1), min(v2, v3)) == 0u) cand |= 1u << g;
    }

    // ---- rare path: full 40-word check, warp-convergent ----
    if (__ballot_sync(0xFFFFFFFFu, cand != 0u)) {
        #pragma unroll 1
        for (int g = 0; g < 4; g++) {
            unsigned gl = __ballot_sync(0xFFFFFFFFu, (cand >> g) & 1u);
            while (gl) {
                int src = __ffs(gl) - 1;
                gl &= gl - 1u;
                int sbase = g * 128 + src * 4;
                #pragma unroll 1
                for (int k = 0; k < 4; k++) {
                    int b = sbase + k;
                    const unsigned* xr = d_xbits[b];
                    unsigned xa = xr[lane];
                    bool ok = (((p_lo & ~xa) | (n_lo & xa)) == 0u);
                    if (lane < NWORD - 32) {
                        unsigned xb = xr[lane + 32];
                        ok = ok && (((p_hi & ~xb) | (n_hi & xb)) == 0u);
                    }
                    if (__all_sync(0xFFFFFFFFu, ok) && lane == 0)
                        atomicAdd(&d_votes[b * A_CLS + a], sg);
                }
            }
        }
    }

    // ---- completion ticket; last block clips and writes the output ----
    __syncthreads();
    if (threadIdx.x == 0) {
        __threadfence();                        // release votes
        unsigned t = atomicAdd(&d_done, 1u);
        sLast = (t == gridDim.x - 1);
    }
    __syncthreads();
    if (sLast) {
        __threadfence();                        // acquire votes
        // T dtype is ambiguous (python int in the reference): small
        // non-negative bit-patterns -> int32, anything else -> float32 bits.
        int ti = *tptr;
        float T = (ti >= 0 && ti < (1 << 23)) ? (float)ti : __int_as_float(ti);
        for (int i = threadIdx.x; i < B_SMP * A_CLS; i += blockDim.x) {
            float v = d_votes[i];
            out[i] = fminf(fmaxf(v, -T), T);    // out is [B, A] = same layout
        }
    }
}

// ---------------------------------------------------------------------------
extern "C" void kernel_launch(void* const* d_in, const int* in_sizes, int n_in,
                              void* d_out, int out_size) {
    const float* x  = (const float*)d_in[0];  // binary_features [512, 1180]
    const float* ta = (const float*)d_in[1];  // ta_state [50, 1024, 2, 1180]
    const float* cs = (const float*)d_in[2];  // clause_sign [50, 1024]
    const int*   Tp = (const int*)  d_in[3];  // T scalar

    (void)in_sizes; (void)n_in; (void)out_size;

    // 1. pack x bitmasks + zero votes/ticket: 512 warps
    pack_x_kernel<<<64, 256>>>(x);
    // 2. fused ta-pack + eval + vote + clip: warp per clause, 8 warps/block
    fused_kernel<<<AC / 8, 256>>>(ta, cs, Tp, (float*)d_out);
}

// round 9
// speedup vs baseline: 1.1697x; 1.1697x over previous
#include <cuda_runtime.h>
#include <cstdint>

// Problem constants
#define A_CLS 50
#define C_CL  1024
#define F_LIT 1180
#define B_SMP 512
#define AC    (A_CLS * C_CL)     // 51200 clauses
#define NWORD 40                 // 10 float4-iterations x 4 ballot-words
#define BCHUNK 64                // samples per eval block

// Scratch (static __device__ globals — no runtime allocation)
// Bit order: iteration i covers literals [i*128, i*128+128); lane l's float4
// holds literals i*128+l*4 .. +3; ballot word (4i+j) packs component j across
// lanes. The SAME permutation is used for x and ta masks -> logic is exact.
// masks[i][ac] is a uint4 = words (4i..4i+3) for clause ac (STG.128 stores).
__device__ uint4    d_maskPos[10][AC];
__device__ uint4    d_maskNeg[10][AC];
__device__ uint4    d_xbits[B_SMP][10];
__device__ unsigned d_x0[B_SMP];          // dense word-0 copy for the eval screen

// ---------------------------------------------------------------------------
// Fused pack: warps [0, AC*2) threshold+pack ta_state rows (483 MB, DRAM-
// bound, one warp per row -> max occupancy + clean coalescing); warps
// [AC*2, AC*2+512) pack the feature rows. One launch.
// ---------------------------------------------------------------------------
__global__ void pack_kernel(const float* __restrict__ ta,
                            const float* __restrict__ x) {
    int warp = (blockIdx.x * blockDim.x + threadIdx.x) >> 5;
    int lane = threadIdx.x & 31;

    if (warp < AC * 2) {
        int ac  = warp >> 1;
        int pol = warp & 1;
        const float4* row4 = reinterpret_cast<const float4*>(ta + (size_t)warp * F_LIT);
        uint4* dst = pol ? &d_maskNeg[0][ac] : &d_maskPos[0][ac];
        #pragma unroll
        for (int i = 0; i < 10; i++) {
            float4 v = make_float4(0.f, 0.f, 0.f, 0.f);
            if (i * 128 + lane * 4 < F_LIT) v = __ldg(&row4[i * 32 + lane]);
            unsigned b0 = __ballot_sync(0xFFFFFFFFu, v.x > 16.0f);
            unsigned b1 = __ballot_sync(0xFFFFFFFFu, v.y > 16.0f);
            unsigned b2 = __ballot_sync(0xFFFFFFFFu, v.z > 16.0f);
            unsigned b3 = __ballot_sync(0xFFFFFFFFu, v.w > 16.0f);
            if (lane == 0) dst[(size_t)i * AC] = make_uint4(b0, b1, b2, b3);
        }
    } else if (warp < AC * 2 + B_SMP) {
        int b = warp - AC * 2;
        const float4* row4 = reinterpret_cast<const float4*>(x + (size_t)b * F_LIT);
        #pragma unroll
        for (int i = 0; i < 10; i++) {
            float4 v = make_float4(0.f, 0.f, 0.f, 0.f);
            if (i * 128 + lane * 4 < F_LIT) v = __ldg(&row4[i * 32 + lane]);
            unsigned b0 = __ballot_sync(0xFFFFFFFFu, v.x > 0.5f);
            unsigned b1 = __ballot_sync(0xFFFFFFFFu, v.y > 0.5f);
            unsigned b2 = __ballot_sync(0xFFFFFFFFu, v.z > 0.5f);
            unsigned b3 = __ballot_sync(0xFFFFFFFFu, v.w > 0.5f);
            if (lane == 0) {
                d_xbits[b][i] = make_uint4(b0, b1, b2, b3);
                if (i == 0) d_x0[b] = b0;
            }
        }
    }
}

// ---------------------------------------------------------------------------
// Eval + vote + clip. Block (a, y) = one class x 64 samples, 256 threads,
// thread owns 4 clauses (c = tid + 256q). Exclusive smem votes -> direct
// clipped store, no global vote buffer, no epilogue kernel.
// Fast path per x-word group: 1 LDS.128 + 16 LOP3 + min-tree + 1 branch
// covering 16 (clause, sample) evals. 4 independent clause chains give the
// ILP that R7's 1-clause/thread version lacked; launch_bounds(256,4) keeps
// the grid at a single wave (400 blocks < 592 slots) with ~64-reg headroom.
// Rare path (P ~ 2^-32 per eval) checks all 40 words from global (L2-hot).
// ---------------------------------------------------------------------------
__global__ __launch_bounds__(256, 4)
void eval_kernel(const float* __restrict__ clause_sign,
                 const int*   __restrict__ tptr,
                 float*       __restrict__ out) {
    __shared__ __align__(16) unsigned sx0[BCHUNK];
    __shared__ float sv[BCHUNK];

    int a   = blockIdx.x;
    int b0  = blockIdx.y * BCHUNK;
    int tid = threadIdx.x;

    if (tid < BCHUNK) {
        sx0[tid] = d_x0[b0 + tid];
        sv[tid]  = 0.0f;
    }
    __syncthreads();

    int      idx[4];
    unsigned p0[4], n0[4];
    float    sg[4];
    #pragma unroll
    for (int q = 0; q < 4; q++) {
        idx[q] = a * C_CL + tid + 256 * q;       // coalesced mask loads
        p0[q]  = d_maskPos[0][idx[q]].x;
        n0[q]  = d_maskNeg[0][idx[q]].x;
        sg[q]  = __ldg(&clause_sign[idx[q]]);
    }

    #pragma unroll
    for (int bl = 0; bl < BCHUNK; bl += 4) {
        uint4 x = *reinterpret_cast<const uint4*>(&sx0[bl]);
        unsigned mall = 0xFFFFFFFFu;
        #pragma unroll
        for (int q = 0; q < 4; q++) {
            unsigned v0 = (p0[q] & ~x.x) | (n0[q] & x.x);
            unsigned v1 = (p0[q] & ~x.y) | (n0[q] & x.y);
            unsigned v2 = (p0[q] & ~x.z) | (n0[q] & x.z);
            unsigned v3 = (p0[q] & ~x.w) | (n0[q] & x.w);
            mall = min(mall, min(min(v0, v1), min(v2, v3)));
        }
        if (mall == 0u) {                        // rare path: recompute + full check
            #pragma unroll 1
            for (int q = 0; q < 4; q++) {
                unsigned vv[4];
                vv[0] = (p0[q] & ~x.x) | (n0[q] & x.x);
                vv[1] = (p0[q] & ~x.y) | (n0[q] & x.y);
                vv[2] = (p0[q] & ~x.z) | (n0[q] & x.z);
                vv[3] = (p0[q] & ~x.w) | (n0[q] & x.w);
                #pragma unroll 1
                for (int j = 0; j < 4; j++) {
                    if (vv[j] != 0u) continue;
                    int b = b0 + bl + j;
                    const unsigned* xr = reinterpret_cast<const unsigned*>(&d_xbits[b][0]);
                    bool fire = true;
                    #pragma unroll 1
                    for (int w = 1; w < NWORD && fire; w++) {
                        unsigned xx = xr[w];
                        unsigned pw = reinterpret_cast<const unsigned*>(&d_maskPos[w >> 2][idx[q]])[w & 3];
                        unsigned nw = reinterpret_cast<const unsigned*>(&d_maskNeg[w >> 2][idx[q]])[w & 3];
                        if ((pw & ~xx) | (nw & xx)) fire = false;
                    }
                    if (fire) atomicAdd(&sv[bl + j], sg[q]);
                }
            }
        }
    }
    __syncthreads();

    if (tid < BCHUNK) {
        // T dtype is ambiguous (python int in the reference): small
        // non-negative bit-patterns -> int32, anything else -> float32 bits.
        int ti = *tptr;
        float T = (ti >= 0 && ti < (1 << 23)) ? (float)ti : __int_as_float(ti);
        float v = sv[tid];
        out[(b0 + tid) * A_CLS + a] = fminf(fmaxf(v, -T), T);
    }
}

// ---------------------------------------------------------------------------
extern "C" void kernel_launch(void* const* d_in, const int* in_sizes, int n_in,
                              void* d_out, int out_size) {
    const float* x  = (const float*)d_in[0];  // binary_features [512, 1180]
    const float* ta = (const float*)d_in[1];  // ta_state [50, 1024, 2, 1180]
    const float* cs = (const float*)d_in[2];  // clause_sign [50, 1024]
    const int*   Tp = (const int*)  d_in[3];  // T scalar

    (void)in_sizes; (void)n_in; (void)out_size;

    // 1. fused pack (ta masks + x bits): 102912 warps, DRAM-bound on 483 MB
    {
        long long threads = ((long long)AC * 2 + B_SMP) * 32;
        pack_kernel<<<(int)((threads + 255) / 256), 256>>>(ta, x);
    }
    // 2. eval + vote + clip: grid (A, 8), 256 threads, 4 clauses/thread
    {
        dim3 grid(A_CLS, B_SMP / BCHUNK);
        eval_kernel<<<grid, 256>>>(cs, Tp, (float*)d_out);
    }
}

// round 10
// speedup vs baseline: 1.1892x; 1.0166x over previous
#include <cuda_runtime.h>
#include <cstdint>

// Problem constants
#define A_CLS 50
#define C_CL  1024
#define F_LIT 1180
#define B_SMP 512
#define AC    (A_CLS * C_CL)     // 51200 clauses
#define NWORD 40                 // 10 float4-iterations x 4 ballot-words
#define BCHUNK 32                // samples per eval block (grid = 50 x 16)

// Scratch (static __device__ globals — no runtime allocation)
// Bit order: iteration i covers literals [i*128, i*128+128); lane l's float4
// holds literals i*128+l*4 .. +3; ballot word (4i+j) packs component j across
// lanes. The SAME permutation is used for x and ta masks -> logic is exact.
// masks[i][ac] is a uint4 = words (4i..4i+3) for clause ac (STG.128 stores).
__device__ uint4    d_maskPos[10][AC];
__device__ uint4    d_maskNeg[10][AC];
__device__ uint4    d_xbits[B_SMP][10];
__device__ unsigned d_x0[B_SMP];          // dense word-0 copy for the eval screen

// ---------------------------------------------------------------------------
// Fused pack: warps [0, AC*2) threshold+pack ta_state rows (483 MB, DRAM-
// bound, one warp per row -> max MLP + clean coalescing); warps
// [AC*2, AC*2+512) pack the feature rows. At HBM roofline (~84% spec).
// ---------------------------------------------------------------------------
__global__ void pack_kernel(const float* __restrict__ ta,
                            const float* __restrict__ x) {
    int warp = (blockIdx.x * blockDim.x + threadIdx.x) >> 5;
    int lane = threadIdx.x & 31;

    if (warp < AC * 2) {
        int ac  = warp >> 1;
        int pol = warp & 1;
        const float4* row4 = reinterpret_cast<const float4*>(ta + (size_t)warp * F_LIT);
        uint4* dst = pol ? &d_maskNeg[0][ac] : &d_maskPos[0][ac];
        #pragma unroll
        for (int i = 0; i < 10; i++) {
            float4 v = make_float4(0.f, 0.f, 0.f, 0.f);
            if (i * 128 + lane * 4 < F_LIT) v = __ldg(&row4[i * 32 + lane]);
            unsigned b0 = __ballot_sync(0xFFFFFFFFu, v.x > 16.0f);
            unsigned b1 = __ballot_sync(0xFFFFFFFFu, v.y > 16.0f);
            unsigned b2 = __ballot_sync(0xFFFFFFFFu, v.z > 16.0f);
            unsigned b3 = __ballot_sync(0xFFFFFFFFu, v.w > 16.0f);
            if (lane == 0) dst[(size_t)i * AC] = make_uint4(b0, b1, b2, b3);
        }
    } else if (warp < AC * 2 + B_SMP) {
        int b = warp - AC * 2;
        const float4* row4 = reinterpret_cast<const float4*>(x + (size_t)b * F_LIT);
        #pragma unroll
        for (int i = 0; i < 10; i++) {
            float4 v = make_float4(0.f, 0.f, 0.f, 0.f);
            if (i * 128 + lane * 4 < F_LIT) v = __ldg(&row4[i * 32 + lane]);
            unsigned b0 = __ballot_sync(0xFFFFFFFFu, v.x > 0.5f);
            unsigned b1 = __ballot_sync(0xFFFFFFFFu, v.y > 0.5f);
            unsigned b2 = __ballot_sync(0xFFFFFFFFu, v.z > 0.5f);
            unsigned b3 = __ballot_sync(0xFFFFFFFFu, v.w > 0.5f);
            if (lane == 0) {
                d_xbits[b][i] = make_uint4(b0, b1, b2, b3);
                if (i == 0) d_x0[b] = b0;
            }
        }
    }
}

// ---------------------------------------------------------------------------
// Eval + vote + clip. Block (a, y) = one class x 32 samples, 256 threads,
// thread owns 4 clauses (c = tid + 256q). Exclusive smem votes -> direct
// clipped store, no global vote buffer, no epilogue kernel.
//
// HOT loop: 8 groups x (1 LDS.128 + 16 LOP3 + min-tree); the rare-candidate
// decision is accumulated into a bitmask — NO rare-path code inside the
// unrolled loop (R9's inlined copies were ~50KB of SASS and thrashed the
// 32KB L1.5 I$). COLD block after the loop re-derives candidates from smem.
// Grid (50, 16) = 800 blocks ~ 5.4 blocks/SM restores occupancy (R9: 2.7).
// ---------------------------------------------------------------------------
__global__ __launch_bounds__(256, 6)
void eval_kernel(const float* __restrict__ clause_sign,
                 const int*   __restrict__ tptr,
                 float*       __restrict__ out) {
    __shared__ __align__(16) unsigned sx0[BCHUNK];
    __shared__ float sv[BCHUNK];

    int a   = blockIdx.x;
    int b0  = blockIdx.y * BCHUNK;
    int tid = threadIdx.x;

    if (tid < BCHUNK) {
        sx0[tid] = d_x0[b0 + tid];
        sv[tid]  = 0.0f;
    }
    __syncthreads();

    int      base = a * C_CL + tid;
    unsigned p0[4], n0[4];
    #pragma unroll
    for (int q = 0; q < 4; q++) {
        p0[q] = d_maskPos[0][base + 256 * q].x;  // coalesced
        n0[q] = d_maskNeg[0][base + 256 * q].x;
    }

    // ---- hot loop: candidate screen only ----
    unsigned cand = 0u;
    #pragma unroll
    for (int g = 0; g < BCHUNK / 4; g++) {
        uint4 x = *reinterpret_cast<const uint4*>(&sx0[g * 4]);
        unsigned mall = 0xFFFFFFFFu;
        #pragma unroll
        for (int q = 0; q < 4; q++) {
            unsigned v0 = (p0[q] & ~x.x) | (n0[q] & x.x);   // 1 LOP3 each
            unsigned v1 = (p0[q] & ~x.y) | (n0[q] & x.y);
            unsigned v2 = (p0[q] & ~x.z) | (n0[q] & x.z);
            unsigned v3 = (p0[q] & ~x.w) | (n0[q] & x.w);
            mall = min(mall, min(min(v0, v1), min(v2, v3)));
        }
        if (mall == 0u) cand |= 1u << g;
    }

    // ---- cold block: full 40-word verification for candidates ----
    if (cand != 0u) {
        #pragma unroll 1
        for (int g = 0; g < BCHUNK / 4; g++) {
            if (!((cand >> g) & 1u)) continue;
            #pragma unroll 1
            for (int j = 0; j < 4; j++) {
                int b = b0 + g * 4 + j;
                unsigned xw0 = sx0[g * 4 + j];
                #pragma unroll 1
                for (int q = 0; q < 4; q++) {
                    int idx = base + 256 * q;
                    if (((p0[q] & ~xw0) | (n0[q] & xw0)) != 0u) continue;
                    const unsigned* xr = reinterpret_cast<const unsigned*>(&d_xbits[b][0]);
                    bool fire = true;
                    #pragma unroll 1
                    for (int w = 1; w < NWORD && fire; w++) {
                        unsigned xx = xr[w];
                        unsigned pw = reinterpret_cast<const unsigned*>(&d_maskPos[w >> 2][idx])[w & 3];
                        unsigned nw = reinterpret_cast<const unsigned*>(&d_maskNeg[w >> 2][idx])[w & 3];
                        if ((pw & ~xx) | (nw & xx)) fire = false;
                    }
                    if (fire)
                        atomicAdd(&sv[g * 4 + j], __ldg(&clause_sign[idx]));
                }
            }
        }
    }
    __syncthreads();

    if (tid < BCHUNK) {
        // T dtype is ambiguous (python int in the reference): small
        // non-negative bit-patterns -> int32, anything else -> float32 bits.
        int ti = *tptr;
        float T = (ti >= 0 && ti < (1 << 23)) ? (float)ti : __int_as_float(ti);
        float v = sv[tid];
        out[(b0 + tid) * A_CLS + a] = fminf(fmaxf(v, -T), T);
    }
}

// ---------------------------------------------------------------------------
extern "C" void kernel_launch(void* const* d_in, const int* in_sizes, int n_in,
                              void* d_out, int out_size) {
    const float* x  = (const float*)d_in[0];  // binary_features [512, 1180]
    const float* ta = (const float*)d_in[1];  // ta_state [50, 1024, 2, 1180]
    const float* cs = (const float*)d_in[2];  // clause_sign [50, 1024]
    const int*   Tp = (const int*)  d_in[3];  // T scalar

    (void)in_sizes; (void)n_in; (void)out_size;

    // 1. fused pack (ta masks + x bits): 102912 warps, DRAM-bound on 483 MB
    {
        long long threads = ((long long)AC * 2 + B_SMP) * 32;
        pack_kernel<<<(int)((threads + 255) / 256), 256>>>(ta, x);
    }
    // 2. eval + vote + clip: grid (50, 16), 256 threads, 4 clauses/thread
    {
        dim3 grid(A_CLS, B_SMP / BCHUNK);
        eval_kernel<<<grid, 256>>>(cs, Tp, (float*)d_out);
    }
}